// round 7
// baseline (speedup 1.0000x reference)
#include <cuda_runtime.h>
#include <cuda_bf16.h>
#include <math.h>

// ---------------------------------------------------------------------------
// Model constants (fixed by the reference)
// ---------------------------------------------------------------------------
#define SLEN   2048
#define DMODEL 1024
#define NHQ    16
#define NKV    4
#define HD     64
#define IDIM   4096
#define VOCAB  32000
#define NLAYER 4
#define EPSF   1e-6f

#define SD  (SLEN * DMODEL)            // 2,097,152
#define SKD (SLEN * NKV * HD)          // 524,288
#define SI  (SLEN * IDIM)              // 8,388,608

// scratch: h, x, q, o (SD each) + k, v (SKD each) + gate, up (SI each)
__device__ float g_scratch[4 * SD + 2 * SKD + 2 * SI];

// ---------------------------------------------------------------------------
// Embedding gather: h[s,:] = embed[ids[s],:]
// ---------------------------------------------------------------------------
__global__ void embed_kernel(const float* __restrict__ embed,
                             const int* __restrict__ ids,
                             float* __restrict__ h) {
    int s = blockIdx.x;
    int id = ids[s];
    const float4* src = (const float4*)(embed + (size_t)id * DMODEL);
    float4* dst = (float4*)(h + (size_t)s * DMODEL);
    for (int i = threadIdx.x; i < DMODEL / 4; i += blockDim.x) dst[i] = src[i];
}

// ---------------------------------------------------------------------------
// RMSNorm: out = w * x * rsqrt(mean(x^2) + eps). One block per row, 256 thr.
// ---------------------------------------------------------------------------
__global__ __launch_bounds__(256) void rmsnorm_kernel(const float* __restrict__ x,
                                                      const float* __restrict__ w,
                                                      float* __restrict__ out) {
    int s = blockIdx.x;
    int t = threadIdx.x;
    const float4* row = (const float4*)(x + (size_t)s * DMODEL);
    float4 xv = row[t];  // 256 threads * 4 = 1024
    float ss = xv.x * xv.x + xv.y * xv.y + xv.z * xv.z + xv.w * xv.w;
#pragma unroll
    for (int o = 16; o; o >>= 1) ss += __shfl_xor_sync(0xffffffffu, ss, o);
    __shared__ float wsum[8];
    __shared__ float s_inv;
    if ((t & 31) == 0) wsum[t >> 5] = ss;
    __syncthreads();
    if (t == 0) {
        float tot = 0.f;
#pragma unroll
        for (int i = 0; i < 8; i++) tot += wsum[i];
        s_inv = rsqrtf(tot * (1.0f / DMODEL) + EPSF);
    }
    __syncthreads();
    float inv = s_inv;
    float4 wv = ((const float4*)w)[t];
    float4 r;
    r.x = wv.x * (xv.x * inv);
    r.y = wv.y * (xv.y * inv);
    r.z = wv.z * (xv.z * inv);
    r.w = wv.w * (xv.w * inv);
    ((float4*)(out + (size_t)s * DMODEL))[t] = r;
}

// ---------------------------------------------------------------------------
// RoPE in place. Block = (32 lanes, n_heads). One block per sequence position.
// Angles computed in fp64 to track the fp32 reference pipeline closely.
// ---------------------------------------------------------------------------
__global__ void rope_kernel(float* __restrict__ x, int n_heads) {
    int s = blockIdx.x;
    int i = threadIdx.x;   // 0..31 (rotary pair index)
    int h = threadIdx.y;   // head
    __shared__ float s_cs[32], s_sn[32];
    if (h == 0) {
        // inv_freq = 10000^(-i/32), rounded to fp32 like the reference,
        // then angle = fp32(s * inv_freq); sin/cos of that angle in fp64.
        float inv_f = (float)pow(10000.0, -(double)i / 32.0);
        float angf = (float)s * inv_f;
        s_cs[i] = (float)cos((double)angf);
        s_sn[i] = (float)sin((double)angf);
    }
    __syncthreads();
    float cs = s_cs[i], sn = s_sn[i];
    float* p = x + (size_t)s * (n_heads * HD) + h * HD;
    float x1 = p[i], x2 = p[i + 32];
    p[i]      = x1 * cs - x2 * sn;
    p[i + 32] = x2 * cs + x1 * sn;
}

// ---------------------------------------------------------------------------
// Flash attention (fp32, causal, GQA group=4).
// grid = (SLEN/64, NHQ), 256 threads. Tiles: 64 queries x 32 keys, HD=64.
// Thread (tx=tid&15, ty=tid>>4): 4 query rows (4*ty..), 2 key cols / 4 d cols.
// Smem: Qs[64][64], KtP[64*36] (K^T stride 33 / P stride 36, time-shared),
//       Vs[32][64]. Total 33.8 KB (static, < 48 KB).
// ---------------------------------------------------------------------------
__global__ __launch_bounds__(256) void flash_kernel(const float* __restrict__ q,
                                                    const float* __restrict__ k,
                                                    const float* __restrict__ v,
                                                    float* __restrict__ o) {
    __shared__ float Qs[64 * 64];
    __shared__ float KtP[64 * 36];
    __shared__ float Vs[32 * 64];

    const int qt = blockIdx.x;
    const int h  = blockIdx.y;
    const int kvh = h >> 2;  // G = 4
    const int tid = threadIdx.x;
    const int tx = tid & 15, ty = tid >> 4;

    // Load Q tile (64 rows x 64 d)
    for (int i = tid; i < 1024; i += 256) {
        int r = i >> 4, dseg = (i & 15) << 2;
        *(float4*)(Qs + r * 64 + dseg) =
            *(const float4*)(q + (size_t)(qt * 64 + r) * (NHQ * HD) + h * HD + dseg);
    }

    float m_i[4], l_i[4], acc[4][4];
#pragma unroll
    for (int i = 0; i < 4; i++) {
        m_i[i] = -1e30f; l_i[i] = 0.f;
#pragma unroll
        for (int j = 0; j < 4; j++) acc[i][j] = 0.f;
    }

    const int nkt = (qt + 1) * 2;  // 32-key tiles covering keys <= qt*64+63
    for (int kt = 0; kt < nkt; ++kt) {
        __syncthreads();
        // Load K^T (stride 33) and V (natural) for 32 keys
        for (int i = tid; i < 512; i += 256) {
            int key = i >> 4, dseg = (i & 15) << 2;
            size_t gb = (size_t)(kt * 32 + key) * (NKV * HD) + kvh * HD + dseg;
            float4 k4 = *(const float4*)(k + gb);
            KtP[(dseg + 0) * 33 + key] = k4.x;
            KtP[(dseg + 1) * 33 + key] = k4.y;
            KtP[(dseg + 2) * 33 + key] = k4.z;
            KtP[(dseg + 3) * 33 + key] = k4.w;
            *(float4*)(Vs + key * 64 + dseg) = *(const float4*)(v + gb);
        }
        __syncthreads();

        // S = Q @ K^T  (4x2 micro-tile per thread)
        float sacc[4][2] = {{0.f, 0.f}, {0.f, 0.f}, {0.f, 0.f}, {0.f, 0.f}};
#pragma unroll 4
        for (int kk = 0; kk < 64; kk += 4) {
            float qa[4][4];
#pragma unroll
            for (int i = 0; i < 4; i++)
                *(float4*)qa[i] = *(const float4*)(Qs + (4 * ty + i) * 64 + kk);
#pragma unroll
            for (int u = 0; u < 4; u++) {
                float kc0 = KtP[(kk + u) * 33 + 2 * tx];
                float kc1 = KtP[(kk + u) * 33 + 2 * tx + 1];
#pragma unroll
                for (int i = 0; i < 4; i++) {
                    sacc[i][0] += qa[i][u] * kc0;
                    sacc[i][1] += qa[i][u] * kc1;
                }
            }
        }

        // scale + causal mask
        const float scale = 0.125f;  // 1/sqrt(64)
#pragma unroll
        for (int i = 0; i < 4; i++) {
            int qrow = qt * 64 + 4 * ty + i;
#pragma unroll
            for (int j = 0; j < 2; j++) {
                int kcol = kt * 32 + 2 * tx + j;
                float sv = sacc[i][j] * scale;
                sacc[i][j] = (kcol > qrow) ? -1e30f : sv;
            }
        }

        // online softmax (row spread across 16 tx-lanes -> width-16 xor reduce)
#pragma unroll
        for (int i = 0; i < 4; i++) {
            float mx = fmaxf(sacc[i][0], sacc[i][1]);
#pragma unroll
            for (int off = 8; off; off >>= 1)
                mx = fmaxf(mx, __shfl_xor_sync(0xffffffffu, mx, off, 16));
            float mnew = fmaxf(m_i[i], mx);
            float corr = expf(m_i[i] - mnew);
            float p0 = expf(sacc[i][0] - mnew);
            float p1 = expf(sacc[i][1] - mnew);
            float rs = p0 + p1;
#pragma unroll
            for (int off = 8; off; off >>= 1)
                rs += __shfl_xor_sync(0xffffffffu, rs, off, 16);
            l_i[i] = l_i[i] * corr + rs;
            m_i[i] = mnew;
            sacc[i][0] = p0; sacc[i][1] = p1;
#pragma unroll
            for (int j = 0; j < 4; j++) acc[i][j] *= corr;
        }

        __syncthreads();  // done reading K^T; reuse buffer for P (stride 36)
#pragma unroll
        for (int i = 0; i < 4; i++) {
            KtP[(4 * ty + i) * 36 + 2 * tx]     = sacc[i][0];
            KtP[(4 * ty + i) * 36 + 2 * tx + 1] = sacc[i][1];
        }
        __syncthreads();

        // O += P @ V
#pragma unroll 2
        for (int kk = 0; kk < 32; kk += 4) {
            float pa[4][4];
#pragma unroll
            for (int i = 0; i < 4; i++)
                *(float4*)pa[i] = *(const float4*)(KtP + (4 * ty + i) * 36 + kk);
#pragma unroll
            for (int u = 0; u < 4; u++) {
                float4 vv = *(const float4*)(Vs + (kk + u) * 64 + 4 * tx);
#pragma unroll
                for (int i = 0; i < 4; i++) {
                    acc[i][0] += pa[i][u] * vv.x;
                    acc[i][1] += pa[i][u] * vv.y;
                    acc[i][2] += pa[i][u] * vv.z;
                    acc[i][3] += pa[i][u] * vv.w;
                }
            }
        }
    }

    // epilogue: o[s, h*64 + d] = acc / l
#pragma unroll
    for (int i = 0; i < 4; i++) {
        float inv = 1.0f / l_i[i];
        float4 r = make_float4(acc[i][0] * inv, acc[i][1] * inv,
                               acc[i][2] * inv, acc[i][3] * inv);
        *(float4*)(o + (size_t)(qt * 64 + 4 * ty + i) * (NHQ * HD) + h * HD + 4 * tx) = r;
    }
}

// ---------------------------------------------------------------------------
// SGEMM: C[M,N] = A[M,K] @ B[K,N] (+bias[n]) (+=C if RES).
// 128x128x8 tile, 256 threads, 8x8 micro-tile, register prefetch.
// Requires M%128==0, N%128==0, K%8==0 (true for all shapes here).
// ---------------------------------------------------------------------------
template <bool BIAS, bool RES>
__global__ __launch_bounds__(256) void sgemm_kernel(const float* __restrict__ A,
                                                    const float* __restrict__ B,
                                                    const float* __restrict__ bias,
                                                    float* __restrict__ C,
                                                    int M, int N, int K) {
    constexpr int BM = 128, BN = 128, BK = 8;
    __shared__ float As[BK][BM];
    __shared__ float Bs[BK][BN];

    const int tid = threadIdx.x;
    const int tx = tid & 15, ty = tid >> 4;
    const int arow = tid >> 1, acol = (tid & 1) << 2;
    const int brow = tid >> 5, bcol = (tid & 31) << 2;

    const float* Ap = A + (size_t)(blockIdx.y * BM + arow) * K + acol;
    const float* Bp = B + (size_t)brow * N + blockIdx.x * BN + bcol;

    float acc[8][8];
#pragma unroll
    for (int i = 0; i < 8; i++)
#pragma unroll
        for (int j = 0; j < 8; j++) acc[i][j] = 0.f;

    const int kIters = K / BK;
    float4 a4 = *(const float4*)Ap;
    float4 b4 = *(const float4*)Bp;

    for (int it = 0; it < kIters; ++it) {
        As[acol + 0][arow] = a4.x;
        As[acol + 1][arow] = a4.y;
        As[acol + 2][arow] = a4.z;
        As[acol + 3][arow] = a4.w;
        *(float4*)&Bs[brow][bcol] = b4;
        __syncthreads();

        if (it + 1 < kIters) {  // prefetch next tile while computing
            Ap += BK;
            Bp += (size_t)BK * N;
            a4 = *(const float4*)Ap;
            b4 = *(const float4*)Bp;
        }

#pragma unroll
        for (int kk = 0; kk < BK; ++kk) {
            float ra[8], rb[8];
            *(float4*)ra       = *(const float4*)&As[kk][ty * 8];
            *(float4*)(ra + 4) = *(const float4*)&As[kk][ty * 8 + 4];
            *(float4*)rb       = *(const float4*)&Bs[kk][tx * 8];
            *(float4*)(rb + 4) = *(const float4*)&Bs[kk][tx * 8 + 4];
#pragma unroll
            for (int i = 0; i < 8; i++)
#pragma unroll
                for (int j = 0; j < 8; j++) acc[i][j] += ra[i] * rb[j];
        }
        __syncthreads();
    }

    const int row0 = blockIdx.y * BM + ty * 8;
    const int col0 = blockIdx.x * BN + tx * 8;
    float bv[8];
    if (BIAS) {
        *(float4*)bv       = *(const float4*)(bias + col0);
        *(float4*)(bv + 4) = *(const float4*)(bias + col0 + 4);
    }
#pragma unroll
    for (int i = 0; i < 8; i++) {
        float* cp = C + (size_t)(row0 + i) * N + col0;
#pragma unroll
        for (int j0 = 0; j0 < 8; j0 += 4) {
            float4 r = make_float4(acc[i][j0], acc[i][j0 + 1],
                                   acc[i][j0 + 2], acc[i][j0 + 3]);
            if (BIAS) { r.x += bv[j0]; r.y += bv[j0 + 1]; r.z += bv[j0 + 2]; r.w += bv[j0 + 3]; }
            if (RES) {
                float4 old = *(const float4*)(cp + j0);
                r.x += old.x; r.y += old.y; r.z += old.z; r.w += old.w;
            }
            *(float4*)(cp + j0) = r;
        }
    }
}

// ---------------------------------------------------------------------------
// gate = silu(gate) * up (float4 vectorized)
// ---------------------------------------------------------------------------
__global__ void silu_mul_kernel(float4* __restrict__ g, const float4* __restrict__ u, int n4) {
    int i = blockIdx.x * blockDim.x + threadIdx.x;
    if (i < n4) {
        float4 a = g[i];
        float4 b = u[i];
        a.x = a.x / (1.f + expf(-a.x)) * b.x;
        a.y = a.y / (1.f + expf(-a.y)) * b.y;
        a.z = a.z / (1.f + expf(-a.z)) * b.z;
        a.w = a.w / (1.f + expf(-a.w)) * b.w;
        g[i] = a;
    }
}

// ---------------------------------------------------------------------------
// Host orchestration
// ---------------------------------------------------------------------------
extern "C" void kernel_launch(void* const* d_in, const int* in_sizes, int n_in,
                              void* d_out, int out_size) {
    (void)in_sizes; (void)n_in; (void)out_size;
    const float* embed  = (const float*)d_in[0];
    const float* ln1    = (const float*)d_in[1];
    const float* qw     = (const float*)d_in[2];
    const float* qb     = (const float*)d_in[3];
    const float* kw     = (const float*)d_in[4];
    const float* kb     = (const float*)d_in[5];
    const float* vw     = (const float*)d_in[6];
    const float* vb     = (const float*)d_in[7];
    const float* ow     = (const float*)d_in[8];
    const float* ln2    = (const float*)d_in[9];
    const float* gw     = (const float*)d_in[10];
    const float* uw     = (const float*)d_in[11];
    const float* dw     = (const float*)d_in[12];
    const float* norm_w = (const float*)d_in[13];
    const float* lm_w   = (const float*)d_in[14];
    const int*   ids    = (const int*)d_in[15];
    float* out = (float*)d_out;

    float* base = nullptr;
    cudaGetSymbolAddress((void**)&base, g_scratch);
    float* h    = base;
    float* x    = h + SD;
    float* q    = x + SD;
    float* o    = q + SD;
    float* kbuf = o + SD;
    float* vbuf = kbuf + SKD;
    float* gate = vbuf + SKD;
    float* up   = gate + SI;

    embed_kernel<<<SLEN, 256>>>(embed, ids, h);

    for (int l = 0; l < NLAYER; ++l) {
        rmsnorm_kernel<<<SLEN, 256>>>(h, ln1 + (size_t)l * DMODEL, x);

        sgemm_kernel<true, false><<<dim3(DMODEL / 128, SLEN / 128), 256>>>(
            x, qw + (size_t)l * DMODEL * (NHQ * HD), qb + (size_t)l * (NHQ * HD),
            q, SLEN, NHQ * HD, DMODEL);
        sgemm_kernel<true, false><<<dim3((NKV * HD) / 128, SLEN / 128), 256>>>(
            x, kw + (size_t)l * DMODEL * (NKV * HD), kb + (size_t)l * (NKV * HD),
            kbuf, SLEN, NKV * HD, DMODEL);
        sgemm_kernel<true, false><<<dim3((NKV * HD) / 128, SLEN / 128), 256>>>(
            x, vw + (size_t)l * DMODEL * (NKV * HD), vb + (size_t)l * (NKV * HD),
            vbuf, SLEN, NKV * HD, DMODEL);

        rope_kernel<<<SLEN, dim3(32, NHQ)>>>(q, NHQ);
        rope_kernel<<<SLEN, dim3(32, NKV)>>>(kbuf, NKV);

        flash_kernel<<<dim3(SLEN / 64, NHQ), 256>>>(q, kbuf, vbuf, o);

        sgemm_kernel<false, true><<<dim3(DMODEL / 128, SLEN / 128), 256>>>(
            o, ow + (size_t)l * (NHQ * HD) * DMODEL, nullptr,
            h, SLEN, DMODEL, NHQ * HD);

        rmsnorm_kernel<<<SLEN, 256>>>(h, ln2 + (size_t)l * DMODEL, x);

        sgemm_kernel<false, false><<<dim3(IDIM / 128, SLEN / 128), 256>>>(
            x, gw + (size_t)l * DMODEL * IDIM, nullptr, gate, SLEN, IDIM, DMODEL);
        sgemm_kernel<false, false><<<dim3(IDIM / 128, SLEN / 128), 256>>>(
            x, uw + (size_t)l * DMODEL * IDIM, nullptr, up, SLEN, IDIM, DMODEL);

        silu_mul_kernel<<<(SI / 4 + 255) / 256, 256>>>((float4*)gate, (const float4*)up, SI / 4);

        sgemm_kernel<false, true><<<dim3(DMODEL / 128, SLEN / 128), 256>>>(
            gate, dw + (size_t)l * IDIM * DMODEL, nullptr, h, SLEN, DMODEL, IDIM);
    }

    rmsnorm_kernel<<<SLEN, 256>>>(h, norm_w, x);
    sgemm_kernel<false, false><<<dim3(VOCAB / 128, SLEN / 128), 256>>>(
        x, lm_w, nullptr, out, SLEN, VOCAB, DMODEL);
}